// round 1
// baseline (speedup 1.0000x reference)
#include <cuda_runtime.h>
#include <cuda_bf16.h>
#include <stdint.h>

// Problem constants
#define N_NODES_MAX 100000
#define N_EDGES_MAX 1600000
#define C_IN  128
#define C_HID 128
#define C_OUT 64

// Scratch (device globals; no allocation allowed)
__device__ float g_H1[N_NODES_MAX * C_HID];   // x @ W1
__device__ float g_A1[N_NODES_MAX * C_HID];   // aggregated layer1 (pre-bias/relu)
__device__ float g_H2[N_NODES_MAX * C_OUT];   // relu(A1+b1) @ W2
__device__ float g_deg[N_NODES_MAX];          // degree, then dis = rsqrt(deg)
__device__ int   g_src[N_EDGES_MAX];
__device__ int   g_dst[N_EDGES_MAX];
__device__ int   g_is64;

// ---------------------------------------------------------------------------
// dtype detection: int64 edge ids < 2^31 have zero high words; int32 data at
// those positions is random node ids (nonzero w.h.p.)
__global__ void k_detect(const int* __restrict__ ei32) {
    int lane = threadIdx.x;
    int v = ei32[2 * lane + 1];
    unsigned b = __ballot_sync(0xFFFFFFFFu, v != 0);
    if (lane == 0) g_is64 = (b == 0) ? 1 : 0;
}

__global__ void k_init_deg(int n) {
    int i = blockIdx.x * blockDim.x + threadIdx.x;
    if (i < n) g_deg[i] = 1.0f;  // self-loop
}

// Canonicalize edges to int32 + count degrees (dst side)
__global__ void k_convert_count(const void* __restrict__ ei, int E) {
    int e = blockIdx.x * blockDim.x + threadIdx.x;
    if (e >= E) return;
    int s, d;
    if (g_is64) {
        const long long* p = (const long long*)ei;
        s = (int)p[e]; d = (int)p[E + e];
    } else {
        const int* p = (const int*)ei;
        s = p[e]; d = p[E + e];
    }
    g_src[e] = s;
    g_dst[e] = d;
    atomicAdd(&g_deg[d], 1.0f);
}

__global__ void k_rsqrt(int n) {
    int i = blockIdx.x * blockDim.x + threadIdx.x;
    if (i < n) g_deg[i] = rsqrtf(g_deg[i]);
}

// ---------------------------------------------------------------------------
// GEMM1: H1 = x @ W1 ; A1 = dis^2 * H1  (self-loop term)
// Block: 256 thr (8 warps), 32 rows/block, 4 rows/warp, lane owns cols 4l..4l+3
__global__ void __launch_bounds__(256) k_gemm1(
    const float* __restrict__ x, const float* __restrict__ W, int n)
{
    extern __shared__ float sm[];
    float4* Ws4 = (float4*)sm;                    // [128][32] float4 = 64KB
    float*  Xs  = sm + C_IN * C_HID;              // [32][128] = 16KB

    int tid = threadIdx.x;
    const float4* Wg = (const float4*)W;
    #pragma unroll
    for (int i = tid; i < (C_IN * C_HID) / 4; i += 256) Ws4[i] = Wg[i];

    int rowBase = blockIdx.x * 32;
    float4* Xs4 = (float4*)Xs;
    for (int i = tid; i < 32 * (C_IN / 4); i += 256) {
        int r = i >> 5, c = i & 31;
        int gr = rowBase + r;
        Xs4[i] = (gr < n) ? ((const float4*)x)[(size_t)gr * 32 + c]
                          : make_float4(0.f, 0.f, 0.f, 0.f);
    }
    __syncthreads();

    int warp = tid >> 5, lane = tid & 31;
    int r0 = warp * 4;
    float4 acc0 = {0,0,0,0}, acc1 = {0,0,0,0}, acc2 = {0,0,0,0}, acc3 = {0,0,0,0};

    #pragma unroll 4
    for (int k = 0; k < C_IN; k++) {
        float4 w = Ws4[k * 32 + lane];
        float x0 = Xs[(r0 + 0) * C_IN + k];
        float x1 = Xs[(r0 + 1) * C_IN + k];
        float x2 = Xs[(r0 + 2) * C_IN + k];
        float x3 = Xs[(r0 + 3) * C_IN + k];
        acc0.x += x0 * w.x; acc0.y += x0 * w.y; acc0.z += x0 * w.z; acc0.w += x0 * w.w;
        acc1.x += x1 * w.x; acc1.y += x1 * w.y; acc1.z += x1 * w.z; acc1.w += x1 * w.w;
        acc2.x += x2 * w.x; acc2.y += x2 * w.y; acc2.z += x2 * w.z; acc2.w += x2 * w.w;
        acc3.x += x3 * w.x; acc3.y += x3 * w.y; acc3.z += x3 * w.z; acc3.w += x3 * w.w;
    }

    float4 accs[4] = {acc0, acc1, acc2, acc3};
    #pragma unroll
    for (int r = 0; r < 4; r++) {
        int gr = rowBase + r0 + r;
        if (gr < n) {
            float di = g_deg[gr];
            float d2 = di * di;
            float4 h = accs[r];
            ((float4*)g_H1)[(size_t)gr * 32 + lane] = h;
            float4 a = {h.x * d2, h.y * d2, h.z * d2, h.w * d2};
            ((float4*)g_A1)[(size_t)gr * 32 + lane] = a;
        }
    }
}

// ---------------------------------------------------------------------------
// Scatter layer1: one warp per edge; lane covers 4 floats via red.v4.f32
__global__ void __launch_bounds__(256) k_scatter1(int E) {
    int gid = blockIdx.x * blockDim.x + threadIdx.x;
    int e = gid >> 5;
    int lane = threadIdx.x & 31;
    if (e >= E) return;
    int s = g_src[e], d = g_dst[e];
    float nrm = g_deg[s] * g_deg[d];
    float4 h = ((const float4*)g_H1)[(size_t)s * 32 + lane];
    float4 m = {h.x * nrm, h.y * nrm, h.z * nrm, h.w * nrm};
    float* p = g_A1 + (size_t)d * C_HID + lane * 4;
    asm volatile("red.global.add.v4.f32 [%0], {%1, %2, %3, %4};"
                 :: "l"(p), "f"(m.x), "f"(m.y), "f"(m.z), "f"(m.w) : "memory");
}

// ---------------------------------------------------------------------------
// GEMM2: z = relu(A1 + b1); H2 = z @ W2; out = dis^2*H2 + b2
// lane owns cols 2l, 2l+1 (N=64)
__global__ void __launch_bounds__(256) k_gemm2(
    const float* __restrict__ W2, const float* __restrict__ b1,
    const float* __restrict__ b2, float* __restrict__ out, int n)
{
    extern __shared__ float sm[];
    float2* Ws2 = (float2*)sm;                    // [128][32] float2 = 32KB
    float*  Xs  = sm + C_HID * C_OUT;             // [32][128] = 16KB

    int tid = threadIdx.x;
    const float2* Wg = (const float2*)W2;
    #pragma unroll
    for (int i = tid; i < (C_HID * C_OUT) / 2; i += 256) Ws2[i] = Wg[i];

    int rowBase = blockIdx.x * 32;
    float4* Xs4 = (float4*)Xs;
    for (int i = tid; i < 32 * (C_HID / 4); i += 256) {
        int r = i >> 5, c = i & 31;
        int gr = rowBase + r;
        float4 v = make_float4(0.f, 0.f, 0.f, 0.f);
        if (gr < n) {
            v = ((const float4*)g_A1)[(size_t)gr * 32 + c];
            v.x = fmaxf(v.x + __ldg(&b1[c * 4 + 0]), 0.f);
            v.y = fmaxf(v.y + __ldg(&b1[c * 4 + 1]), 0.f);
            v.z = fmaxf(v.z + __ldg(&b1[c * 4 + 2]), 0.f);
            v.w = fmaxf(v.w + __ldg(&b1[c * 4 + 3]), 0.f);
        }
        Xs4[i] = v;
    }
    __syncthreads();

    int warp = tid >> 5, lane = tid & 31;
    int r0 = warp * 4;
    float2 acc0 = {0,0}, acc1 = {0,0}, acc2 = {0,0}, acc3 = {0,0};

    #pragma unroll 4
    for (int k = 0; k < C_HID; k++) {
        float2 w = Ws2[k * 32 + lane];
        float x0 = Xs[(r0 + 0) * C_HID + k];
        float x1 = Xs[(r0 + 1) * C_HID + k];
        float x2 = Xs[(r0 + 2) * C_HID + k];
        float x3 = Xs[(r0 + 3) * C_HID + k];
        acc0.x += x0 * w.x; acc0.y += x0 * w.y;
        acc1.x += x1 * w.x; acc1.y += x1 * w.y;
        acc2.x += x2 * w.x; acc2.y += x2 * w.y;
        acc3.x += x3 * w.x; acc3.y += x3 * w.y;
    }

    float2 accs[4] = {acc0, acc1, acc2, acc3};
    float bb0 = __ldg(&b2[lane * 2 + 0]);
    float bb1 = __ldg(&b2[lane * 2 + 1]);
    #pragma unroll
    for (int r = 0; r < 4; r++) {
        int gr = rowBase + r0 + r;
        if (gr < n) {
            float di = g_deg[gr];
            float d2 = di * di;
            float2 h = accs[r];
            ((float2*)g_H2)[(size_t)gr * 32 + lane] = h;
            float2 o = {h.x * d2 + bb0, h.y * d2 + bb1};
            ((float2*)out)[(size_t)gr * 32 + lane] = o;
        }
    }
}

// ---------------------------------------------------------------------------
// Scatter layer2: 2 edges per warp (64 cols = 16 lanes x float4)
__global__ void __launch_bounds__(256) k_scatter2(float* __restrict__ out, int E) {
    int gid = blockIdx.x * blockDim.x + threadIdx.x;
    int wrp = gid >> 5;
    int lane = threadIdx.x & 31;
    int e = wrp * 2 + (lane >> 4);
    int l16 = lane & 15;
    if (e >= E) return;
    int s = g_src[e], d = g_dst[e];
    float nrm = g_deg[s] * g_deg[d];
    float4 h = ((const float4*)g_H2)[(size_t)s * 16 + l16];
    float4 m = {h.x * nrm, h.y * nrm, h.z * nrm, h.w * nrm};
    float* p = out + (size_t)d * C_OUT + l16 * 4;
    asm volatile("red.global.add.v4.f32 [%0], {%1, %2, %3, %4};"
                 :: "l"(p), "f"(m.x), "f"(m.y), "f"(m.z), "f"(m.w) : "memory");
}

// ---------------------------------------------------------------------------
extern "C" void kernel_launch(void* const* d_in, const int* in_sizes, int n_in,
                              void* d_out, int out_size) {
    const float* x  = (const float*)d_in[0];
    const void*  ei = d_in[1];
    const float* W1 = (const float*)d_in[2];
    const float* b1 = (const float*)d_in[3];
    const float* W2 = (const float*)d_in[4];
    const float* b2 = (const float*)d_in[5];
    float* out = (float*)d_out;

    int n = in_sizes[0] / C_IN;        // 100000
    int E = in_sizes[1] / 2;           // 1600000

    // Opt-in to large dynamic smem (idempotent)
    static int smem_set = 0;
    cudaFuncSetAttribute(k_gemm1, cudaFuncAttributeMaxDynamicSharedMemorySize,
                         (C_IN * C_HID + 32 * C_IN) * sizeof(float));
    cudaFuncSetAttribute(k_gemm2, cudaFuncAttributeMaxDynamicSharedMemorySize,
                         (C_HID * C_OUT + 32 * C_HID) * sizeof(float));
    (void)smem_set;

    int nb_nodes = (n + 255) / 256;
    int nb_edges = (E + 255) / 256;

    k_detect<<<1, 32>>>((const int*)ei);
    k_init_deg<<<nb_nodes, 256>>>(n);
    k_convert_count<<<nb_edges, 256>>>(ei, E);
    k_rsqrt<<<nb_nodes, 256>>>(n);

    int gemm_blocks = (n + 31) / 32;
    size_t smem1 = (size_t)(C_IN * C_HID + 32 * C_IN) * sizeof(float);   // 80KB
    size_t smem2 = (size_t)(C_HID * C_OUT + 32 * C_HID) * sizeof(float); // 48KB

    k_gemm1<<<gemm_blocks, 256, smem1>>>(x, W1, n);

    long long thr1 = (long long)E * 32;
    int sb1 = (int)((thr1 + 255) / 256);
    k_scatter1<<<sb1, 256>>>(E);

    k_gemm2<<<gemm_blocks, 256, smem2>>>(W2, b1, b2, out, n);

    long long thr2 = (long long)((E + 1) / 2) * 32;
    int sb2 = (int)((thr2 + 255) / 256);
    k_scatter2<<<sb2, 256>>>(out, E);
}